// round 16
// baseline (speedup 1.0000x reference)
#include <cuda_runtime.h>
#include <math.h>
#include <stdint.h>

#define NB 8
#define CH 128
#define HH 112
#define WW 112
#define HW (HH*WW)          // 12544
#define NC (NB*CH)          // 1024
#define TOT (NB*CH*HW)      // 12,845,056
#define PP 37               // pooled dim (112/3)
#define NPOOL (PP*PP)       // 1369

// ---- scratch (device globals; no allocation in kernel_launch) ----
__device__ float g_z[TOT];           // sym-conv output
__device__ float g_wsym[CH*CH];      // tf32-rounded symmetric weight
__device__ float g_gap[2][NC];       // parity double-buffered GAP
__device__ float g_ent[2][NB];       // parity double-buffered entropy accumulator
__device__ float g_pool[NC*NPOOL];   // pooled h planes [n][c][pos]

__device__ __forceinline__ uint32_t tf32r(float x) {
    uint32_t u;
    asm("cvt.rna.tf32.f32 %0, %1;" : "=r"(u) : "f"(x));
    return u;
}
__device__ __forceinline__ void mma8(float* c, const uint32_t* a, const uint32_t* b) {
    asm volatile(
        "mma.sync.aligned.m16n8k8.row.col.f32.tf32.tf32.f32 "
        "{%0,%1,%2,%3}, {%4,%5,%6,%7}, {%8,%9}, {%0,%1,%2,%3};"
        : "+f"(c[0]), "+f"(c[1]), "+f"(c[2]), "+f"(c[3])
        : "r"(a[0]), "r"(a[1]), "r"(a[2]), "r"(a[3]), "r"(b[0]), "r"(b[1]));
}

// ========= copy x -> h, fused GAP (slot 0) for iter 0, clears ent slots =========
__global__ void copy_gap_kernel(const float* __restrict__ x, float* __restrict__ h) {
    int nc = blockIdx.x;
    const float4* xp = (const float4*)(x + (size_t)nc * HW);
    float4* hp = (float4*)(h + (size_t)nc * HW);
    float s = 0.f;
    for (int i = threadIdx.x; i < HW/4; i += 256) {
        float4 v = xp[i];
        hp[i] = v;
        s += (v.x + v.y) + (v.z + v.w);
    }
    __shared__ float red[256];
    red[threadIdx.x] = s;
    __syncthreads();
    for (int o = 128; o > 0; o >>= 1) {
        if (threadIdx.x < o) red[threadIdx.x] += red[threadIdx.x + o];
        __syncthreads();
    }
    if (threadIdx.x == 0) {
        g_gap[0][nc] = red[0] * (1.f / (float)HW);
        if (nc < NB) { g_ent[0][nc] = 0.f; g_ent[1][nc] = 0.f; }
    }
}

// ================= symmetrize W (+ tf32 rounding) =================
__global__ void wsym_kernel(const float* __restrict__ W) {
    int i = blockIdx.x * 256 + threadIdx.x;   // 16384
    int d = i >> 7, c = i & 127;
    uint32_t u = tf32r(0.5f * (W[d*CH + c] + W[c*CH + d]));
    g_wsym[i] = __uint_as_float(u);
}

// ========== entropy from h (iter 0 only): block per (n, pooled-row, px-chunk) ==========
#define EC 10
#define ECN 4
__global__ void __launch_bounds__(256) ent_kernel(const float* __restrict__ h, int par) {
    __shared__ float pooled[CH][EC+1];
    __shared__ float er[8];
    int b = blockIdx.x;
    int s = b & 3;
    int npy = b >> 2;
    int n = npy / PP;
    int py = npy - n * PP;
    int px0 = s * EC;
    int pw = min(EC, PP - px0);
    int tid = threadIdx.x, wid = tid >> 5, lane = tid & 31;
    const float* hn = h + (size_t)n * CH * HW + (3*py) * WW + 3*px0;

    for (int idx = tid; idx < CH * pw; idx += 256) {
        int c = idx / pw, px = idx - c * pw;
        const float* p = hn + (size_t)c * HW + 3*px;
        float v = 0.f;
#pragma unroll
        for (int r = 0; r < 3; r++) v += p[r*WW] + p[r*WW+1] + p[r*WW+2];
        pooled[c][px] = v * (1.f/9.f);
    }
    __syncthreads();

    float esum = 0.f;
    for (int px = wid; px < pw; px += 8) {
        float v[4];
#pragma unroll
        for (int j = 0; j < 4; j++) v[j] = pooled[j*32 + lane][px];
        float m = fmaxf(fmaxf(v[0], v[1]), fmaxf(v[2], v[3]));
#pragma unroll
        for (int o = 16; o > 0; o >>= 1) m = fmaxf(m, __shfl_xor_sync(0xffffffffu, m, o));
        float ss = 0.f;
#pragma unroll
        for (int j = 0; j < 4; j++) ss += expf(v[j] - m);
#pragma unroll
        for (int o = 16; o > 0; o >>= 1) ss += __shfl_xor_sync(0xffffffffu, ss, o);
        float lse = m + logf(ss);
        float e = 0.f;
#pragma unroll
        for (int j = 0; j < 4; j++) {
            float lp = v[j] - lse;
            e -= expf(lp) * lp;
        }
#pragma unroll
        for (int o = 16; o > 0; o >>= 1) e += __shfl_xor_sync(0xffffffffu, e, o);
        if (lane == 0) esum += e;
    }
    if (lane == 0) er[wid] = esum;
    __syncthreads();
    if (tid == 0) {
        float t = 0.f;
#pragma unroll
        for (int i = 0; i < 8; i++) t += er[i];
        atomicAdd(&g_ent[par][n], t);
    }
}

// ========== entropy from g_pool (iters 1..3): block per (n, pos-chunk) ==========
#define ES_CH 86
__global__ void __launch_bounds__(256) entsm_kernel(int par) {
    __shared__ float ps[CH][ES_CH+1];   // 44544 B
    __shared__ float er[8];
    int n = blockIdx.y;
    int w0 = blockIdx.x * ES_CH;
    int pw = min(ES_CH, NPOOL - w0);
    int tid = threadIdx.x, wid = tid >> 5, lane = tid & 31;
    const float* pp = g_pool + (size_t)n * CH * NPOOL + w0;

    for (int idx = tid; idx < CH * pw; idx += 256) {
        int c = idx / pw, j = idx - c * pw;
        ps[c][j] = pp[(size_t)c * NPOOL + j];
    }
    __syncthreads();

    float esum = 0.f;
    for (int j = wid; j < pw; j += 8) {
        float v[4];
#pragma unroll
        for (int q = 0; q < 4; q++) v[q] = ps[q*32 + lane][j];
        float m = fmaxf(fmaxf(v[0], v[1]), fmaxf(v[2], v[3]));
#pragma unroll
        for (int o = 16; o > 0; o >>= 1) m = fmaxf(m, __shfl_xor_sync(0xffffffffu, m, o));
        float ss = 0.f;
#pragma unroll
        for (int q = 0; q < 4; q++) ss += expf(v[q] - m);
#pragma unroll
        for (int o = 16; o > 0; o >>= 1) ss += __shfl_xor_sync(0xffffffffu, ss, o);
        float lse = m + logf(ss);
        float e = 0.f;
#pragma unroll
        for (int q = 0; q < 4; q++) {
            float lp = v[q] - lse;
            e -= expf(lp) * lp;
        }
#pragma unroll
        for (int o = 16; o > 0; o >>= 1) e += __shfl_xor_sync(0xffffffffu, e, o);
        if (lane == 0) esum += e;
    }
    if (lane == 0) er[wid] = esum;
    __syncthreads();
    if (tid == 0) {
        float t = 0.f;
#pragma unroll
        for (int i = 0; i < 8; i++) t += er[i];
        atomicAdd(&g_ent[par][n], t);
    }
}

// === symmetric 1x1 conv: mma.sync tf32, full A resident, 2 pixel tiles per CTA ===
#define A_ST2 132                      // 132 % 32 == 4 -> conflict-free A frag reads
#define A_FULL (128 * A_ST2)           // 16896 floats (67584 B)
#define B_ST 136                       // 136 % 32 == 8 -> conflict-free B frag reads
#define B_CHUNK (32 * B_ST)            // 4352 floats (17408 B)
#define SYM_SMEM ((A_FULL + 2*B_CHUNK) * 4)   // 102400 B

__global__ void __launch_bounds__(256, 2) symconv_mma(const float* __restrict__ h,
                                                      const float* __restrict__ bias) {
    extern __shared__ float sm[];
    int tid = threadIdx.x, lane = tid & 31, wid = tid >> 5;
    int n = blockIdx.y, p0 = blockIdx.x * 256;
    const float* hb = h + (size_t)n * CH * HW + p0;

    uint32_t sbase = (uint32_t)__cvta_generic_to_shared(sm);
    uint32_t smB[2] = { sbase + A_FULL*4, sbase + A_FULL*4 + B_CHUNK*4 };
    const float* As = sm;
    float* fB[2] = { sm + A_FULL, sm + A_FULL + B_CHUNK };

    // ---- full A load (one cp.async group) ----
#pragma unroll
    for (int r = 0; r < 16; r++) {
        int i = tid + 256*r;
        int m = i >> 5, kg = (i & 31) << 2;
        asm volatile("cp.async.ca.shared.global [%0], [%1], 16;"
            :: "r"(sbase + (uint32_t)(m*A_ST2 + kg)*4u),
               "l"(&g_wsym[m*CH + kg]) : "memory");
    }
    asm volatile("cp.async.commit_group;" ::: "memory");

#define ISSUE_B(K0, BUF) do {                                                       \
        uint32_t bdst = smB[BUF];                                                   \
        _Pragma("unroll")                                                           \
        for (int r = 0; r < 4; r++) {                                               \
            int i = tid + 256*r;                                                    \
            int kk = i >> 5, pg = (i & 31) << 2;                                    \
            asm volatile("cp.async.ca.shared.global [%0], [%1], 16;"                \
                :: "r"(bdst + (uint32_t)(kk*B_ST + pg)*4u),                         \
                   "l"(hbt + (size_t)((K0) + kk)*HW + pg) : "memory");              \
        }                                                                           \
        asm volatile("cp.async.commit_group;" ::: "memory");                        \
    } while (0)

    int m0 = (wid & 3) * 32;
    int n0 = (wid >> 2) * 64;
    int gr = lane >> 2, tg = lane & 3;

#define MMACHUNK(BUF, K0) do {                                                      \
        const float* Bs = fB[BUF];                                                  \
        _Pragma("unroll")                                                           \
        for (int ks = 0; ks < 4; ks++) {                                            \
            int kc = ks * 8;                                                        \
            uint32_t a[2][4], b[8][2];                                              \
            _Pragma("unroll")                                                       \
            for (int i = 0; i < 2; i++) {                                           \
                const float* ap = &As[(m0 + i*16 + gr)*A_ST2 + (K0) + kc + tg];     \
                a[i][0] = __float_as_uint(ap[0]);                                   \
                a[i][1] = __float_as_uint(ap[8*A_ST2]);                             \
                a[i][2] = __float_as_uint(ap[4]);                                   \
                a[i][3] = __float_as_uint(ap[8*A_ST2 + 4]);                         \
            }                                                                       \
            _Pragma("unroll")                                                       \
            for (int j = 0; j < 8; j++) {                                           \
                const float* bp = &Bs[(kc + tg)*B_ST + n0 + j*8 + gr];              \
                b[j][0] = tf32r(bp[0]);                                             \
                b[j][1] = tf32r(bp[4*B_ST]);                                        \
            }                                                                       \
            _Pragma("unroll")                                                       \
            for (int i = 0; i < 2; i++)                                             \
                _Pragma("unroll")                                                   \
                for (int j = 0; j < 8; j++)                                         \
                    mma8(acc[i][j], a[i], b[j]);                                    \
        }                                                                           \
    } while (0)

#pragma unroll 1
    for (int t2 = 0; t2 < 2; t2++) {
        const float* hbt = hb + t2 * 128;
        float acc[2][8][4];
#pragma unroll
        for (int i = 0; i < 2; i++)
#pragma unroll
            for (int j = 0; j < 8; j++)
#pragma unroll
                for (int r = 0; r < 4; r++) acc[i][j][r] = 0.f;

        ISSUE_B(0, 0);
        ISSUE_B(32, 1);
        asm volatile("cp.async.wait_group 1;" ::: "memory");
        __syncthreads();
        MMACHUNK(0, 0);
        __syncthreads();
        ISSUE_B(64, 0);
        asm volatile("cp.async.wait_group 1;" ::: "memory");
        __syncthreads();
        MMACHUNK(1, 32);
        __syncthreads();
        ISSUE_B(96, 1);
        asm volatile("cp.async.wait_group 1;" ::: "memory");
        __syncthreads();
        MMACHUNK(0, 64);
        __syncthreads();
        asm volatile("cp.async.wait_group 0;" ::: "memory");
        __syncthreads();
        MMACHUNK(1, 96);

        float* zb = g_z + (size_t)n * CH * HW + p0 + t2 * 128;
#pragma unroll
        for (int i = 0; i < 2; i++) {
            int r0 = m0 + i*16 + gr;
            float bi0 = bias[r0], bi1 = bias[r0 + 8];
#pragma unroll
            for (int j = 0; j < 8; j++) {
                int col = n0 + j*8 + tg*2;
                float2 v0 = make_float2(acc[i][j][0] + bi0, acc[i][j][1] + bi0);
                float2 v1 = make_float2(acc[i][j][2] + bi1, acc[i][j][3] + bi1);
                *(float2*)&zb[(size_t)r0       * HW + col] = v0;
                *(float2*)&zb[(size_t)(r0 + 8) * HW + col] = v1;
            }
        }
        __syncthreads();   // all B reads done before next tile's ISSUE_B overwrites
    }
#undef ISSUE_B
#undef MMACHUNK
}

// ===== FUSED: gates + gated tri-dilated dwconv + IS-norm + ReLU6 + residual + GAP + pool =====
#define ZS_W 120
#define DWT 512
#define PPT 25
#define DWN_SMEM (ZS_W*ZS_W * 4)           // 57600 bytes (>= HW*4 for h-plane reuse)

__global__ void __launch_bounds__(DWT, 2) dwnorm_kernel(const float* __restrict__ w,
                                                        const float* __restrict__ bias,
                                                        const float* __restrict__ gamma,
                                                        const float* __restrict__ beta,
                                                        const float* __restrict__ gW,
                                                        const float* __restrict__ gb,
                                                        const float* __restrict__ gwe,
                                                        float* __restrict__ h, int t,
                                                        int do_pool) {
    extern __shared__ float smf[];
    float* zs = smf;                  // [120][120]; later reused as h plane [HW]
    __shared__ float red[DWT];
    __shared__ float redq[DWT];
    __shared__ float bc[2];
    __shared__ float bcg[3];

    int nc = blockIdx.x;
    int n = nc >> 7, c = nc & 127;
    int tid = threadIdx.x, wid = tid >> 5, lane = tid & 31;
    const float* zb = g_z + (size_t)nc * HW;
    int par = t & 1;

    if (wid == 0) {
        const float4 gp = *(const float4*)&g_gap[par][n*CH + lane*4];
        const float* gv = (const float*)&gp;
        float s0 = 0.f, s1 = 0.f, s2 = 0.f;
#pragma unroll
        for (int j = 0; j < 4; j++) {
            int cc = lane*4 + j;
            float val = gv[j];
            s0 += val * gW[cc*3+0];
            s1 += val * gW[cc*3+1];
            s2 += val * gW[cc*3+2];
        }
#pragma unroll
        for (int o = 16; o > 0; o >>= 1) {
            s0 += __shfl_xor_sync(0xffffffffu, s0, o);
            s1 += __shfl_xor_sync(0xffffffffu, s1, o);
            s2 += __shfl_xor_sync(0xffffffffu, s2, o);
        }
        if (lane == 0) {
            float ent = g_ent[par][n] * (1.f / (float)NPOOL);
            float l0 = s0 + gb[0] + ent*gwe[0];
            float l1 = s1 + gb[1] + ent*gwe[1];
            float l2 = s2 + gb[2] + ent*gwe[2];
            float m = fmaxf(l0, fmaxf(l1, l2));
            float e0 = expf(l0-m), e1 = expf(l1-m), e2 = expf(l2-m);
            float inv = 1.f / (e0 + e1 + e2);
            bcg[0] = e0*inv; bcg[1] = e1*inv; bcg[2] = e2*inv;
        }
    }

    for (int s = tid; s < ZS_W*ZS_W; s += DWT) {
        int sy = s / ZS_W, sx = s - sy*ZS_W;
        int gy = sy - 4, gx = sx - 4;
        float v = 0.f;
        if ((unsigned)gy < (unsigned)HH && (unsigned)gx < (unsigned)WW)
            v = zb[gy*WW + gx];
        zs[s] = v;
    }
    float wk[9];
#pragma unroll
    for (int k = 0; k < 9; k++) wk[k] = w[c*9 + k];
    float bi = bias[c];
    __syncthreads();
    float g0 = bcg[0], g1 = bcg[1], g2 = bcg[2];

    float yreg[PPT];
    float lsum = 0.f, lsq = 0.f;
#pragma unroll
    for (int r = 0; r < PPT; r++) {
        int p = tid + DWT * r;
        if (p < HW) {
            int py = p / WW, px = p - py*WW;
            const float* zc = zs + (py+4)*ZS_W + (px+4);
            float s1 = 0.f, s2 = 0.f, s4 = 0.f;
#pragma unroll
            for (int ky = 0; ky < 3; ky++)
#pragma unroll
                for (int kx = 0; kx < 3; kx++) {
                    float wv = wk[ky*3 + kx];
                    int dy = ky - 1, dx = kx - 1;
                    s1 += wv * zc[dy*ZS_W + dx];
                    s2 += wv * zc[2*dy*ZS_W + 2*dx];
                    s4 += wv * zc[4*dy*ZS_W + 4*dx];
                }
            float acc = bi + g0*s1 + g1*s2 + g2*s4;
            yreg[r] = acc;
            lsum += acc;
            lsq  += acc * acc;
        }
    }
    red[tid] = lsum;
    redq[tid] = lsq;
    __syncthreads();
    for (int o = DWT/2; o > 0; o >>= 1) {
        if (tid < o) { red[tid] += red[tid + o]; redq[tid] += redq[tid + o]; }
        __syncthreads();
    }
    if (tid == 0) {
        float mean = red[0] * (1.f / (float)HW);
        float var  = redq[0] * (1.f / (float)HW) - mean*mean;
        bc[0] = mean;
        bc[1] = rsqrtf(var + 1e-5f) * gamma[t*CH + c];
    }
    __syncthreads();
    float mean = bc[0], sc = bc[1], bt = beta[t*CH + c];

    // normalize + ReLU6 + residual + GAP; also stash h plane into zs (zs reads are done)
    float* hp = h + (size_t)nc * HW;
    float gs = 0.f;
#pragma unroll
    for (int r = 0; r < PPT; r++) {
        int p = tid + DWT * r;
        if (p < HW) {
            float v = (yreg[r] - mean)*sc + bt;
            v = fminf(fmaxf(v, 0.f), 6.f);
            float hv = hp[p] + v;
            hp[p] = hv;
            zs[p] = hv;
            gs += hv;
        }
    }
    __syncthreads();
    red[tid] = gs;
    __syncthreads();
    for (int o = DWT/2; o > 0; o >>= 1) {
        if (tid < o) red[tid] += red[tid + o];
        __syncthreads();
    }
    if (tid == 0) {
        g_gap[par ^ 1][nc] = red[0] * (1.f / (float)HW);
        if (nc < NB) g_ent[par ^ 1][nc] = 0.f;
    }

    // pool 3x3 windows of the stashed h plane -> g_pool (consumed by entsm next iter)
    if (do_pool) {
        float* pp = g_pool + (size_t)nc * NPOOL;
        for (int wdx = tid; wdx < NPOOL; wdx += DWT) {
            int pyy = wdx / PP, pxx = wdx - pyy*PP;
            const float* base = zs + (3*pyy)*WW + 3*pxx;
            float s = base[0] + base[1] + base[2]
                    + base[WW] + base[WW+1] + base[WW+2]
                    + base[2*WW] + base[2*WW+1] + base[2*WW+2];
            pp[wdx] = s * (1.f/9.f);
        }
    }
}

extern "C" void kernel_launch(void* const* d_in, const int* in_sizes, int n_in,
                              void* d_out, int out_size) {
    const float* x     = (const float*)d_in[0];
    const float* dw_w  = (const float*)d_in[1];
    const float* dw_b  = (const float*)d_in[2];
    const float* sym_w = (const float*)d_in[3];
    const float* sym_b = (const float*)d_in[4];
    const float* gW    = (const float*)d_in[5];
    const float* gb    = (const float*)d_in[6];
    const float* gwe   = (const float*)d_in[7];
    const float* gamma = (const float*)d_in[8];
    const float* beta  = (const float*)d_in[9];
    float* h = (float*)d_out;

    cudaFuncSetAttribute(symconv_mma, cudaFuncAttributeMaxDynamicSharedMemorySize, SYM_SMEM);
    cudaFuncSetAttribute(dwnorm_kernel, cudaFuncAttributeMaxDynamicSharedMemorySize, DWN_SMEM);

    copy_gap_kernel<<<NC, 256>>>(x, h);
    wsym_kernel<<<CH*CH/256, 256>>>(sym_w);

    for (int t = 0; t < 4; t++) {
        if (t == 0)
            ent_kernel<<<NB*PP*ECN, 256>>>(h, 0);
        else
            entsm_kernel<<<dim3((NPOOL + ES_CH - 1)/ES_CH, NB), 256>>>(t & 1);
        symconv_mma<<<dim3(HW/256, NB), 256, SYM_SMEM>>>(h, sym_b);
        dwnorm_kernel<<<NC, DWT, DWN_SMEM>>>(dw_w, dw_b, gamma, beta, gW, gb, gwe, h, t,
                                             t < 3 ? 1 : 0);
    }
}

// round 17
// speedup vs baseline: 1.0864x; 1.0864x over previous
#include <cuda_runtime.h>
#include <cuda_fp16.h>
#include <math.h>
#include <stdint.h>

#define NB 8
#define CH 128
#define HH 112
#define WW 112
#define HW (HH*WW)          // 12544
#define NC (NB*CH)          // 1024
#define TOT (NB*CH*HW)      // 12,845,056
#define PP 37               // pooled dim (112/3)
#define NPOOL (PP*PP)       // 1369

// ---- scratch (device globals; no allocation in kernel_launch) ----
__device__ __half g_z[TOT];      // sym-conv output (fp16; IS-norm absorbs rounding)
__device__ float g_wsym[CH*CH];  // tf32-rounded symmetric weight
__device__ float g_gap[2][NC];   // parity double-buffered GAP
__device__ float g_ent[2][NB];   // parity double-buffered entropy accumulator

__device__ __forceinline__ uint32_t tf32r(float x) {
    uint32_t u;
    asm("cvt.rna.tf32.f32 %0, %1;" : "=r"(u) : "f"(x));
    return u;
}
__device__ __forceinline__ void mma8(float* c, const uint32_t* a, const uint32_t* b) {
    asm volatile(
        "mma.sync.aligned.m16n8k8.row.col.f32.tf32.tf32.f32 "
        "{%0,%1,%2,%3}, {%4,%5,%6,%7}, {%8,%9}, {%0,%1,%2,%3};"
        : "+f"(c[0]), "+f"(c[1]), "+f"(c[2]), "+f"(c[3])
        : "r"(a[0]), "r"(a[1]), "r"(a[2]), "r"(a[3]), "r"(b[0]), "r"(b[1]));
}

// ========= copy x -> h, fused GAP (slot 0) for iter 0, clears ent slots =========
__global__ void copy_gap_kernel(const float* __restrict__ x, float* __restrict__ h) {
    int nc = blockIdx.x;
    const float4* xp = (const float4*)(x + (size_t)nc * HW);
    float4* hp = (float4*)(h + (size_t)nc * HW);
    float s = 0.f;
    for (int i = threadIdx.x; i < HW/4; i += 256) {
        float4 v = xp[i];
        hp[i] = v;
        s += (v.x + v.y) + (v.z + v.w);
    }
    __shared__ float red[256];
    red[threadIdx.x] = s;
    __syncthreads();
    for (int o = 128; o > 0; o >>= 1) {
        if (threadIdx.x < o) red[threadIdx.x] += red[threadIdx.x + o];
        __syncthreads();
    }
    if (threadIdx.x == 0) {
        g_gap[0][nc] = red[0] * (1.f / (float)HW);
        if (nc < NB) { g_ent[0][nc] = 0.f; g_ent[1][nc] = 0.f; }
    }
}

// ================= symmetrize W (+ tf32 rounding) =================
__global__ void wsym_kernel(const float* __restrict__ W) {
    int i = blockIdx.x * 256 + threadIdx.x;   // 16384
    int d = i >> 7, c = i & 127;
    uint32_t u = tf32r(0.5f * (W[d*CH + c] + W[c*CH + d]));
    g_wsym[i] = __uint_as_float(u);
}

// ================= entropy: block per (n, pooled-row, px-chunk) =================
#define EC 10   // px chunk width
#define ECN 4   // chunks per row
__global__ void __launch_bounds__(256) ent_kernel(const float* __restrict__ h, int par) {
    __shared__ float pooled[CH][EC+1];
    __shared__ float er[8];
    int b = blockIdx.x;
    int s = b & 3;
    int npy = b >> 2;
    int n = npy / PP;
    int py = npy - n * PP;
    int px0 = s * EC;
    int pw = min(EC, PP - px0);
    int tid = threadIdx.x, wid = tid >> 5, lane = tid & 31;
    const float* hn = h + (size_t)n * CH * HW + (3*py) * WW + 3*px0;

    for (int idx = tid; idx < CH * pw; idx += 256) {
        int c = idx / pw, px = idx - c * pw;
        const float* p = hn + (size_t)c * HW + 3*px;
        float v = 0.f;
#pragma unroll
        for (int r = 0; r < 3; r++) v += p[r*WW] + p[r*WW+1] + p[r*WW+2];
        pooled[c][px] = v * (1.f/9.f);
    }
    __syncthreads();

    float esum = 0.f;
    for (int px = wid; px < pw; px += 8) {
        float v[4];
#pragma unroll
        for (int j = 0; j < 4; j++) v[j] = pooled[j*32 + lane][px];
        float m = fmaxf(fmaxf(v[0], v[1]), fmaxf(v[2], v[3]));
#pragma unroll
        for (int o = 16; o > 0; o >>= 1) m = fmaxf(m, __shfl_xor_sync(0xffffffffu, m, o));
        float ss = 0.f;
#pragma unroll
        for (int j = 0; j < 4; j++) ss += expf(v[j] - m);
#pragma unroll
        for (int o = 16; o > 0; o >>= 1) ss += __shfl_xor_sync(0xffffffffu, ss, o);
        float lse = m + logf(ss);
        float e = 0.f;
#pragma unroll
        for (int j = 0; j < 4; j++) {
            float lp = v[j] - lse;
            e -= expf(lp) * lp;
        }
#pragma unroll
        for (int o = 16; o > 0; o >>= 1) e += __shfl_xor_sync(0xffffffffu, e, o);
        if (lane == 0) esum += e;
    }
    if (lane == 0) er[wid] = esum;
    __syncthreads();
    if (tid == 0) {
        float t = 0.f;
#pragma unroll
        for (int i = 0; i < 8; i++) t += er[i];
        atomicAdd(&g_ent[par][n], t);
    }
}

// ======= symmetric 1x1 conv: mma.sync tf32, cp.async double-buffered K-chunks =======
#define A_ST 36
#define B_ST 136
#define A_CHUNK (128 * A_ST)
#define B_CHUNK (32 * B_ST)
#define SYM_SMEM ((2*A_CHUNK + 2*B_CHUNK) * 4)   // 71680 bytes

__global__ void __launch_bounds__(256, 2) symconv_mma(const float* __restrict__ h,
                                                      const float* __restrict__ bias) {
    extern __shared__ float sm[];
    int tid = threadIdx.x, lane = tid & 31, wid = tid >> 5;
    int n = blockIdx.y, p0 = blockIdx.x * 128;
    const float* hb = h + (size_t)n * CH * HW + p0;

    uint32_t sbase = (uint32_t)__cvta_generic_to_shared(sm);
    uint32_t smA[2] = { sbase, sbase + A_CHUNK*4 };
    uint32_t smB[2] = { sbase + 2*A_CHUNK*4, sbase + 2*A_CHUNK*4 + B_CHUNK*4 };
    float* fA[2] = { sm, sm + A_CHUNK };
    float* fB[2] = { sm + 2*A_CHUNK, sm + 2*A_CHUNK + B_CHUNK };

#define ISSUE(K0, BUF) do {                                                         \
        uint32_t adst = smA[BUF], bdst = smB[BUF];                                  \
        _Pragma("unroll")                                                           \
        for (int r = 0; r < 4; r++) {                                               \
            int i = tid + 256*r;                                                    \
            int m = i >> 3, kkg = (i & 7) << 2;                                     \
            asm volatile("cp.async.ca.shared.global [%0], [%1], 16;"                \
                :: "r"(adst + (uint32_t)(m*A_ST + kkg)*4u),                         \
                   "l"(&g_wsym[m*CH + (K0) + kkg]) : "memory");                     \
            int kk = i >> 5, pg = (i & 31) << 2;                                    \
            asm volatile("cp.async.ca.shared.global [%0], [%1], 16;"                \
                :: "r"(bdst + (uint32_t)(kk*B_ST + pg)*4u),                         \
                   "l"(hb + (size_t)((K0) + kk)*HW + pg) : "memory");               \
        }                                                                           \
        asm volatile("cp.async.commit_group;" ::: "memory");                        \
    } while (0)

    int m0 = (wid & 3) * 32;
    int n0 = (wid >> 2) * 64;
    int gr = lane >> 2, tg = lane & 3;

    float acc[2][8][4];
#pragma unroll
    for (int i = 0; i < 2; i++)
#pragma unroll
        for (int j = 0; j < 8; j++)
#pragma unroll
            for (int r = 0; r < 4; r++) acc[i][j][r] = 0.f;

#define MMACHUNK(BUF) do {                                                          \
        const float* As = fA[BUF];                                                  \
        const float* Bs = fB[BUF];                                                  \
        _Pragma("unroll")                                                           \
        for (int ks = 0; ks < 4; ks++) {                                            \
            int kc = ks * 8;                                                        \
            uint32_t a[2][4], b[8][2];                                              \
            _Pragma("unroll")                                                       \
            for (int i = 0; i < 2; i++) {                                           \
                const float* ap = &As[(m0 + i*16 + gr)*A_ST + kc + tg];             \
                a[i][0] = __float_as_uint(ap[0]);                                   \
                a[i][1] = __float_as_uint(ap[8*A_ST]);                              \
                a[i][2] = __float_as_uint(ap[4]);                                   \
                a[i][3] = __float_as_uint(ap[8*A_ST + 4]);                          \
            }                                                                       \
            _Pragma("unroll")                                                       \
            for (int j = 0; j < 8; j++) {                                           \
                const float* bp = &Bs[(kc + tg)*B_ST + n0 + j*8 + gr];              \
                b[j][0] = tf32r(bp[0]);                                             \
                b[j][1] = tf32r(bp[4*B_ST]);                                        \
            }                                                                       \
            _Pragma("unroll")                                                       \
            for (int i = 0; i < 2; i++)                                             \
                _Pragma("unroll")                                                   \
                for (int j = 0; j < 8; j++)                                         \
                    mma8(acc[i][j], a[i], b[j]);                                    \
        }                                                                           \
    } while (0)

    ISSUE(0, 0);
    ISSUE(32, 1);
    asm volatile("cp.async.wait_group 1;" ::: "memory");
    __syncthreads();
    MMACHUNK(0);
    __syncthreads();
    ISSUE(64, 0);
    asm volatile("cp.async.wait_group 1;" ::: "memory");
    __syncthreads();
    MMACHUNK(1);
    __syncthreads();
    ISSUE(96, 1);
    asm volatile("cp.async.wait_group 1;" ::: "memory");
    __syncthreads();
    MMACHUNK(0);
    __syncthreads();
    asm volatile("cp.async.wait_group 0;" ::: "memory");
    __syncthreads();
    MMACHUNK(1);

    __half* zb = g_z + (size_t)n * CH * HW + p0;
#pragma unroll
    for (int i = 0; i < 2; i++) {
        int r0 = m0 + i*16 + gr;
        float bi0 = bias[r0], bi1 = bias[r0 + 8];
#pragma unroll
        for (int j = 0; j < 8; j++) {
            int col = n0 + j*8 + tg*2;
            *(__half2*)&zb[(size_t)r0       * HW + col] =
                __floats2half2_rn(acc[i][j][0] + bi0, acc[i][j][1] + bi0);
            *(__half2*)&zb[(size_t)(r0 + 8) * HW + col] =
                __floats2half2_rn(acc[i][j][2] + bi1, acc[i][j][3] + bi1);
        }
    }
#undef ISSUE
#undef MMACHUNK
}

// ===== FUSED: inline gates + gated tri-dilated dwconv + IS-norm + ReLU6 + residual + GAP =====
// 512 threads; y kept in registers (25/thread); smem = z halo plane only.
#define ZS_W 120
#define DWT 512
#define PPT 25
#define DWN_SMEM (ZS_W*ZS_W * 4)           // 57600 bytes

__global__ void __launch_bounds__(DWT, 2) dwnorm_kernel(const float* __restrict__ w,
                                                        const float* __restrict__ bias,
                                                        const float* __restrict__ gamma,
                                                        const float* __restrict__ beta,
                                                        const float* __restrict__ gW,
                                                        const float* __restrict__ gb,
                                                        const float* __restrict__ gwe,
                                                        float* __restrict__ h, int t) {
    extern __shared__ float smf[];
    float* zs = smf;                  // [120][120]
    __shared__ float red[DWT];
    __shared__ float redq[DWT];
    __shared__ float bc[2];           // mean, scale
    __shared__ float bcg[3];          // gates

    int nc = blockIdx.x;
    int n = nc >> 7, c = nc & 127;
    int tid = threadIdx.x, wid = tid >> 5, lane = tid & 31;
    const __half* zb = g_z + (size_t)nc * HW;
    int par = t & 1;

    // warp 0: gates for this sample (reads stable parity slots)
    if (wid == 0) {
        const float4 gp = *(const float4*)&g_gap[par][n*CH + lane*4];
        const float* gv = (const float*)&gp;
        float s0 = 0.f, s1 = 0.f, s2 = 0.f;
#pragma unroll
        for (int j = 0; j < 4; j++) {
            int cc = lane*4 + j;
            float val = gv[j];
            s0 += val * gW[cc*3+0];
            s1 += val * gW[cc*3+1];
            s2 += val * gW[cc*3+2];
        }
#pragma unroll
        for (int o = 16; o > 0; o >>= 1) {
            s0 += __shfl_xor_sync(0xffffffffu, s0, o);
            s1 += __shfl_xor_sync(0xffffffffu, s1, o);
            s2 += __shfl_xor_sync(0xffffffffu, s2, o);
        }
        if (lane == 0) {
            float ent = g_ent[par][n] * (1.f / (float)NPOOL);
            float l0 = s0 + gb[0] + ent*gwe[0];
            float l1 = s1 + gb[1] + ent*gwe[1];
            float l2 = s2 + gb[2] + ent*gwe[2];
            float m = fmaxf(l0, fmaxf(l1, l2));
            float e0 = expf(l0-m), e1 = expf(l1-m), e2 = expf(l2-m);
            float inv = 1.f / (e0 + e1 + e2);
            bcg[0] = e0*inv; bcg[1] = e1*inv; bcg[2] = e2*inv;
        }
    }

    // load z plane (fp16 -> f32) with halo 4 (zero-padded)
    for (int s = tid; s < ZS_W*ZS_W; s += DWT) {
        int sy = s / ZS_W, sx = s - sy*ZS_W;
        int gy = sy - 4, gx = sx - 4;
        float v = 0.f;
        if ((unsigned)gy < (unsigned)HH && (unsigned)gx < (unsigned)WW)
            v = __half2float(zb[gy*WW + gx]);
        zs[s] = v;
    }
    float wk[9];
#pragma unroll
    for (int k = 0; k < 9; k++) wk[k] = w[c*9 + k];
    float bi = bias[c];
    __syncthreads();
    float g0 = bcg[0], g1 = bcg[1], g2 = bcg[2];

    // dwconv into registers + local stats
    float yreg[PPT];
    float lsum = 0.f, lsq = 0.f;
#pragma unroll
    for (int r = 0; r < PPT; r++) {
        int p = tid + DWT * r;
        if (p < HW) {
            int py = p / WW, px = p - py*WW;
            const float* zc = zs + (py+4)*ZS_W + (px+4);
            float s1 = 0.f, s2 = 0.f, s4 = 0.f;
#pragma unroll
            for (int ky = 0; ky < 3; ky++)
#pragma unroll
                for (int kx = 0; kx < 3; kx++) {
                    float wv = wk[ky*3 + kx];
                    int dy = ky - 1, dx = kx - 1;
                    s1 += wv * zc[dy*ZS_W + dx];
                    s2 += wv * zc[2*dy*ZS_W + 2*dx];
                    s4 += wv * zc[4*dy*ZS_W + 4*dx];
                }
            float acc = bi + g0*s1 + g1*s2 + g2*s4;
            yreg[r] = acc;
            lsum += acc;
            lsq  += acc * acc;
        }
    }
    red[tid] = lsum;
    redq[tid] = lsq;
    __syncthreads();
    for (int o = DWT/2; o > 0; o >>= 1) {
        if (tid < o) { red[tid] += red[tid + o]; redq[tid] += redq[tid + o]; }
        __syncthreads();
    }
    if (tid == 0) {
        float mean = red[0] * (1.f / (float)HW);
        float var  = redq[0] * (1.f / (float)HW) - mean*mean;
        bc[0] = mean;
        bc[1] = rsqrtf(var + 1e-5f) * gamma[t*CH + c];
    }
    __syncthreads();
    float mean = bc[0], sc = bc[1], bt = beta[t*CH + c];

    // normalize + ReLU6 + residual + GAP (coalesced scalar access)
    float* hp = h + (size_t)nc * HW;
    float gs = 0.f;
#pragma unroll
    for (int r = 0; r < PPT; r++) {
        int p = tid + DWT * r;
        if (p < HW) {
            float v = (yreg[r] - mean)*sc + bt;
            v = fminf(fmaxf(v, 0.f), 6.f);
            float hv = hp[p] + v;
            hp[p] = hv;
            gs += hv;
        }
    }
    __syncthreads();
    red[tid] = gs;
    __syncthreads();
    for (int o = DWT/2; o > 0; o >>= 1) {
        if (tid < o) red[tid] += red[tid + o];
        __syncthreads();
    }
    if (tid == 0) {
        g_gap[par ^ 1][nc] = red[0] * (1.f / (float)HW);
        if (nc < NB) g_ent[par ^ 1][nc] = 0.f;
    }
}

extern "C" void kernel_launch(void* const* d_in, const int* in_sizes, int n_in,
                              void* d_out, int out_size) {
    const float* x     = (const float*)d_in[0];
    const float* dw_w  = (const float*)d_in[1];
    const float* dw_b  = (const float*)d_in[2];
    const float* sym_w = (const float*)d_in[3];
    const float* sym_b = (const float*)d_in[4];
    const float* gW    = (const float*)d_in[5];
    const float* gb    = (const float*)d_in[6];
    const float* gwe   = (const float*)d_in[7];
    const float* gamma = (const float*)d_in[8];
    const float* beta  = (const float*)d_in[9];
    float* h = (float*)d_out;

    cudaFuncSetAttribute(symconv_mma, cudaFuncAttributeMaxDynamicSharedMemorySize, SYM_SMEM);
    cudaFuncSetAttribute(dwnorm_kernel, cudaFuncAttributeMaxDynamicSharedMemorySize, DWN_SMEM);

    copy_gap_kernel<<<NC, 256>>>(x, h);
    wsym_kernel<<<CH*CH/256, 256>>>(sym_w);

    for (int t = 0; t < 4; t++) {
        ent_kernel<<<NB*PP*ECN, 256>>>(h, t & 1);
        symconv_mma<<<dim3(HW/128, NB), 256, SYM_SMEM>>>(h, sym_b);
        dwnorm_kernel<<<NC, DWT, DWN_SMEM>>>(dw_w, dw_b, gamma, beta, gW, gb, gwe, h, t);
    }
}